// round 3
// baseline (speedup 1.0000x reference)
#include <cuda_runtime.h>
#include <math.h>

// Problem constants
// B=16, C=256, H=W=64, K=7, C/4=64, C*K*K=12544

// ---- scratch (static device allocations: allowed) ----
__device__ float g_pooled[16 * 256];            // [B, C]
__device__ float g_h[16 * 64];                  // [B, C/4]
__device__ float g_fused[16 * 256 * 49];        // [B, C, 49]
__device__ float g_tmp[16u * 256u * 64u * 64u]; // [B, C, H, W] depthwise output (64 MB)

// ---------------------------------------------------------------------------
// Kernel 1: global average pool.  one block per (b,c), 256 threads.
// ---------------------------------------------------------------------------
__global__ void pool_kernel(const float* __restrict__ x) {
    int bc = blockIdx.x;
    const float4* xp = (const float4*)(x + (size_t)bc * 4096);
    float s = 0.f;
    #pragma unroll 4
    for (int i = threadIdx.x; i < 1024; i += 256) {
        float4 v = xp[i];
        s += (v.x + v.y) + (v.z + v.w);
    }
    __shared__ float red[256];
    red[threadIdx.x] = s;
    __syncthreads();
    for (int off = 128; off > 0; off >>= 1) {
        if (threadIdx.x < off) red[threadIdx.x] += red[threadIdx.x + off];
        __syncthreads();
    }
    if (threadIdx.x == 0) g_pooled[bc] = red[0] * (1.f / 4096.f);
}

// ---------------------------------------------------------------------------
// Kernel 2: h = gelu(pooled @ w1^T + b1), exact gelu.  grid=B, block=64.
// ---------------------------------------------------------------------------
__global__ void mlp1_kernel(const float* __restrict__ w1, const float* __restrict__ b1) {
    int b = blockIdx.x;
    int j = threadIdx.x;   // 0..63
    __shared__ float p[256];
    for (int i = threadIdx.x; i < 256; i += 64) p[i] = g_pooled[b * 256 + i];
    __syncthreads();
    float s = b1[j];
    const float* wr = w1 + (size_t)j * 256;
    #pragma unroll 8
    for (int c = 0; c < 256; c++) s += p[c] * wr[c];
    // exact GELU: 0.5*x*(1+erf(x/sqrt(2)))
    g_h[b * 64 + j] = 0.5f * s * (1.0f + erff(s * 0.70710678118654752f));
}

// ---------------------------------------------------------------------------
// Kernel 3: fused[b,c,q] = dw[c,q] + b2[c*49+q] + sum_j h[b,j]*w2[(c*49+q),j]
// grid = 16*49 = 784 blocks of 256 (each block stays within one b).
// ---------------------------------------------------------------------------
__global__ void fuse_kernel(const float* __restrict__ dw,
                            const float* __restrict__ w2,
                            const float* __restrict__ b2) {
    int gid = blockIdx.x * 256 + threadIdx.x;  // 0 .. 200703
    int b = gid / 12544;
    int wi = gid - b * 12544;                  // c*49 + q
    __shared__ float hs[64];
    if (threadIdx.x < 64) hs[threadIdx.x] = g_h[b * 64 + threadIdx.x];
    __syncthreads();
    const float* w2r = w2 + (size_t)wi * 64;
    float s = b2[wi] + dw[wi];
    #pragma unroll 8
    for (int j = 0; j < 64; j++) s += hs[j] * w2r[j];
    g_fused[gid] = s;
}

// ---------------------------------------------------------------------------
// Kernel 4: per-sample depthwise 7x7 conv (cross-correlation), pad=3.
// grid = (4 row-tiles, 4096 bc), 256 threads (64 cols x 4 thread-rows),
// each thread computes 4 consecutive output rows -> 70 LDS per 4 outputs.
// ---------------------------------------------------------------------------
__global__ void dw_kernel(const float* __restrict__ x) {
    int bc = blockIdx.y;
    int rowBase = blockIdx.x * 16;
    const float* xp = x + (size_t)bc * 4096;

    __shared__ float s[22 * 70];   // rows [rowBase-3, rowBase+18], cols [-3, 66]
    __shared__ float wsh[49];

    if (threadIdx.x < 49) wsh[threadIdx.x] = g_fused[bc * 49 + threadIdx.x];

    for (int i = threadIdx.x; i < 22 * 70; i += 256) {
        int r = i / 70, cc = i - r * 70;
        int gr = rowBase + r - 3, gc = cc - 3;
        s[i] = (gr >= 0 && gr < 64 && gc >= 0 && gc < 64) ? xp[gr * 64 + gc] : 0.f;
    }
    __syncthreads();

    float w[49];
    #pragma unroll
    for (int q = 0; q < 49; q++) w[q] = wsh[q];

    int col = threadIdx.x & 63;
    int lr0 = (threadIdx.x >> 6) * 4;   // first of 4 local output rows

    float acc[4] = {0.f, 0.f, 0.f, 0.f};
    #pragma unroll
    for (int r = 0; r < 10; r++) {      // local smem rows lr0 .. lr0+9
        float v[7];
        #pragma unroll
        for (int kx = 0; kx < 7; kx++) v[kx] = s[(lr0 + r) * 70 + col + kx];
        #pragma unroll
        for (int i = 0; i < 4; i++) {
            int ky = r - i;
            if (ky >= 0 && ky < 7) {
                #pragma unroll
                for (int kx = 0; kx < 7; kx++) acc[i] += v[kx] * w[ky * 7 + kx];
            }
        }
    }
    #pragma unroll
    for (int i = 0; i < 4; i++) {
        g_tmp[(size_t)bc * 4096 + (rowBase + lr0 + i) * 64 + col] = acc[i];
    }
}

// ---------------------------------------------------------------------------
// Kernel 5: pointwise 1x1 conv == batched SGEMM
//   out[b, o, hw] = sum_c pw[o, c] * tmp[b, c, hw]
// per b: M=256 (o), N=4096 (hw), K=256 (c).  128x128x16 tile, 8x8 per thread.
// ---------------------------------------------------------------------------
__global__ void __launch_bounds__(256, 1) pw_gemm(const float* __restrict__ pw,
                                                  float* __restrict__ out) {
    __shared__ float As[16][132];  // [k][m], padded
    __shared__ float Bs[16][132];  // [k][n], padded

    int b = blockIdx.z;
    int tileM = blockIdx.y;   // 0..1
    int tileN = blockIdx.x;   // 0..31
    const float* Bb = g_tmp + (size_t)b * 256 * 4096;
    float* Cb = out + (size_t)b * 256 * 4096;

    int tid = threadIdx.x;
    int tcol = tid & 15;
    int trow = tid >> 4;
    int m0 = trow * 8;
    int n0 = tcol * 8;

    float acc[8][8];
    #pragma unroll
    for (int i = 0; i < 8; i++)
        #pragma unroll
        for (int j = 0; j < 8; j++) acc[i][j] = 0.f;

    for (int k0 = 0; k0 < 256; k0 += 16) {
        // load A tile (128 rows x 16 k), stored transposed As[k][m]
        #pragma unroll
        for (int l = 0; l < 2; l++) {
            int lin = tid + l * 256;           // 0..511
            int row = lin >> 2;                // 0..127
            int kseg = (lin & 3) * 4;          // 0,4,8,12
            float4 a = *(const float4*)&pw[(size_t)(tileM * 128 + row) * 256 + k0 + kseg];
            As[kseg + 0][row] = a.x;
            As[kseg + 1][row] = a.y;
            As[kseg + 2][row] = a.z;
            As[kseg + 3][row] = a.w;
        }
        // load B tile (16 k x 128 n)
        #pragma unroll
        for (int l = 0; l < 2; l++) {
            int lin = tid + l * 256;
            int k = lin >> 5;                  // 0..15
            int nseg = (lin & 31) * 4;         // 0..124
            float4 v = *(const float4*)&Bb[(size_t)(k0 + k) * 4096 + tileN * 128 + nseg];
            *(float4*)&Bs[k][nseg] = v;
        }
        __syncthreads();

        #pragma unroll
        for (int k = 0; k < 16; k++) {
            float a[8], bb[8];
            *(float4*)&a[0]  = *(const float4*)&As[k][m0];
            *(float4*)&a[4]  = *(const float4*)&As[k][m0 + 4];
            *(float4*)&bb[0] = *(const float4*)&Bs[k][n0];
            *(float4*)&bb[4] = *(const float4*)&Bs[k][n0 + 4];
            #pragma unroll
            for (int i = 0; i < 8; i++)
                #pragma unroll
                for (int j = 0; j < 8; j++) acc[i][j] += a[i] * bb[j];
        }
        __syncthreads();
    }

    #pragma unroll
    for (int i = 0; i < 8; i++) {
        float* cp = &Cb[(size_t)(tileM * 128 + m0 + i) * 4096 + tileN * 128 + n0];
        *(float4*)cp       = make_float4(acc[i][0], acc[i][1], acc[i][2], acc[i][3]);
        *(float4*)(cp + 4) = make_float4(acc[i][4], acc[i][5], acc[i][6], acc[i][7]);
    }
}

// ---------------------------------------------------------------------------
// launch
// ---------------------------------------------------------------------------
extern "C" void kernel_launch(void* const* d_in, const int* in_sizes, int n_in,
                              void* d_out, int out_size) {
    const float* x   = (const float*)d_in[0];  // [16,256,64,64]
    const float* dw  = (const float*)d_in[1];  // [256,1,7,7]
    const float* pwm = (const float*)d_in[2];  // [256,256]
    const float* w1  = (const float*)d_in[3];  // [64,256]
    const float* b1  = (const float*)d_in[4];  // [64]
    const float* w2  = (const float*)d_in[5];  // [12544,64]
    const float* b2  = (const float*)d_in[6];  // [12544]
    float* out = (float*)d_out;                // [16,256,64,64] fp32

    pool_kernel<<<4096, 256>>>(x);
    mlp1_kernel<<<16, 64>>>(w1, b1);
    fuse_kernel<<<784, 256>>>(dw, w2, b2);
    dw_kernel<<<dim3(4, 4096), 256>>>(x);
    pw_gemm<<<dim3(32, 2, 16), 256>>>(pwm, out);
}

// round 5
// speedup vs baseline: 1.1729x; 1.1729x over previous
#include <cuda_runtime.h>
#include <cuda_bf16.h>
#include <math.h>
#include <stdint.h>

#define DINLINE __device__ __forceinline__

// Problem constants: B=16, C=256, H=W=64, K=7, C/4=64, C*K*K=12544

// ---- scratch (static device allocations: allowed) ----
__device__ __align__(128) float g_pooled[16 * 256];            // [B, C]
__device__ __align__(128) float g_h[16 * 64];                  // [B, C/4]
__device__ __align__(128) float g_fused[16 * 256 * 49];        // [B, C, 49]
__device__ __align__(128) float g_tmp[16u * 256u * 64u * 64u]; // [B, C, H, W] depthwise out
__device__ __align__(128) __nv_bfloat16 g_pw_hi[256 * 256];    // bf16 hi split of pw
__device__ __align__(128) __nv_bfloat16 g_pw_lo[256 * 256];    // bf16 lo split of pw

// ===========================================================================
// sm_80-era PTX helpers (legal on plain sm_100 target)
// ===========================================================================
DINLINE uint32_t smem_u32(const void* p) {
    uint32_t a;
    asm("{ .reg .u64 t; cvta.to.shared.u64 t, %1; cvt.u32.u64 %0, t; }" : "=r"(a) : "l"(p));
    return a;
}
DINLINE void ldsm_x4(uint32_t* r, uint32_t addr) {
    asm volatile("ldmatrix.sync.aligned.m8n8.x4.shared.b16 {%0,%1,%2,%3}, [%4];"
                 : "=r"(r[0]), "=r"(r[1]), "=r"(r[2]), "=r"(r[3]) : "r"(addr));
}
DINLINE void ldsm_x4_t(uint32_t* r, uint32_t addr) {
    asm volatile("ldmatrix.sync.aligned.m8n8.x4.trans.shared.b16 {%0,%1,%2,%3}, [%4];"
                 : "=r"(r[0]), "=r"(r[1]), "=r"(r[2]), "=r"(r[3]) : "r"(addr));
}
DINLINE void mma_bf16(float* d, const uint32_t* a, const uint32_t* b) {
    asm volatile(
        "mma.sync.aligned.m16n8k16.row.col.f32.bf16.bf16.f32 "
        "{%0,%1,%2,%3}, {%4,%5,%6,%7}, {%8,%9}, {%0,%1,%2,%3};"
        : "+f"(d[0]), "+f"(d[1]), "+f"(d[2]), "+f"(d[3])
        : "r"(a[0]), "r"(a[1]), "r"(a[2]), "r"(a[3]), "r"(b[0]), "r"(b[1]));
}

// ---------------------------------------------------------------------------
// Kernel 0: split pw weights into bf16 hi/lo
// ---------------------------------------------------------------------------
__global__ void pw_split(const float* __restrict__ pw) {
    int i = blockIdx.x * 256 + threadIdx.x;   // 65536 elems
    float v = pw[i];
    __nv_bfloat16 h = __float2bfloat16(v);
    g_pw_hi[i] = h;
    g_pw_lo[i] = __float2bfloat16(v - __bfloat162float(h));
}

// ---------------------------------------------------------------------------
// Kernel 1: global average pool
// ---------------------------------------------------------------------------
__global__ void pool_kernel(const float* __restrict__ x) {
    int bc = blockIdx.x;
    const float4* xp = (const float4*)(x + (size_t)bc * 4096);
    float s = 0.f;
    #pragma unroll 4
    for (int i = threadIdx.x; i < 1024; i += 256) {
        float4 v = xp[i];
        s += (v.x + v.y) + (v.z + v.w);
    }
    __shared__ float red[256];
    red[threadIdx.x] = s;
    __syncthreads();
    for (int off = 128; off > 0; off >>= 1) {
        if (threadIdx.x < off) red[threadIdx.x] += red[threadIdx.x + off];
        __syncthreads();
    }
    if (threadIdx.x == 0) g_pooled[bc] = red[0] * (1.f / 4096.f);
}

// ---------------------------------------------------------------------------
// Kernel 2: h = gelu(pooled @ w1^T + b1)
// ---------------------------------------------------------------------------
__global__ void mlp1_kernel(const float* __restrict__ w1, const float* __restrict__ b1) {
    int b = blockIdx.x;
    int j = threadIdx.x;   // 0..63
    __shared__ float p[256];
    for (int i = threadIdx.x; i < 256; i += 64) p[i] = g_pooled[b * 256 + i];
    __syncthreads();
    float s = b1[j];
    const float* wr = w1 + (size_t)j * 256;
    #pragma unroll 8
    for (int c = 0; c < 256; c++) s += p[c] * wr[c];
    g_h[b * 64 + j] = 0.5f * s * (1.0f + erff(s * 0.70710678118654752f));
}

// ---------------------------------------------------------------------------
// Kernel 3: fused dynamic+static depthwise weights
// ---------------------------------------------------------------------------
__global__ void fuse_kernel(const float* __restrict__ dw,
                            const float* __restrict__ w2,
                            const float* __restrict__ b2) {
    int gid = blockIdx.x * 256 + threadIdx.x;
    int b = gid / 12544;
    int wi = gid - b * 12544;
    __shared__ float hs[64];
    if (threadIdx.x < 64) hs[threadIdx.x] = g_h[b * 64 + threadIdx.x];
    __syncthreads();
    const float* w2r = w2 + (size_t)wi * 64;
    float s = b2[wi] + dw[wi];
    #pragma unroll 8
    for (int j = 0; j < 64; j++) s += hs[j] * w2r[j];
    g_fused[gid] = s;
}

// ---------------------------------------------------------------------------
// Kernel 4: per-sample depthwise 7x7 conv, pad=3.  4 rows/thread,
// weights pinned into registers via asm barrier.
// ---------------------------------------------------------------------------
__global__ void __launch_bounds__(256, 2) dw_kernel(const float* __restrict__ x) {
    int bc = blockIdx.y;
    int rowBase = blockIdx.x * 16;
    const float* xp = x + (size_t)bc * 4096;

    __shared__ float s[22 * 70];
    __shared__ float wsh[49];

    if (threadIdx.x < 49) wsh[threadIdx.x] = g_fused[bc * 49 + threadIdx.x];

    for (int i = threadIdx.x; i < 22 * 70; i += 256) {
        int r = i / 70, cc = i - r * 70;
        int gr = rowBase + r - 3, gc = cc - 3;
        s[i] = (gr >= 0 && gr < 64 && gc >= 0 && gc < 64) ? xp[gr * 64 + gc] : 0.f;
    }
    __syncthreads();

    float w[49];
    #pragma unroll
    for (int q = 0; q < 49; q++) w[q] = wsh[q];
    #pragma unroll
    for (int q = 0; q < 49; q++) asm volatile("" : "+f"(w[q]));

    int col = threadIdx.x & 63;
    int lr0 = (threadIdx.x >> 6) * 4;

    float acc[4] = {0.f, 0.f, 0.f, 0.f};
    #pragma unroll
    for (int r = 0; r < 10; r++) {
        float v[7];
        #pragma unroll
        for (int kx = 0; kx < 7; kx++) v[kx] = s[(lr0 + r) * 70 + col + kx];
        #pragma unroll
        for (int i = 0; i < 4; i++) {
            int ky = r - i;
            if (ky >= 0 && ky < 7) {
                #pragma unroll
                for (int kx = 0; kx < 7; kx++) acc[i] += v[kx] * w[ky * 7 + kx];
            }
        }
    }
    #pragma unroll
    for (int i = 0; i < 4; i++) {
        g_tmp[(size_t)bc * 4096 + (rowBase + lr0 + i) * 64 + col] = acc[i];
    }
}

// ---------------------------------------------------------------------------
// Kernel 5: pointwise 1x1 conv == batched GEMM via mma.sync bf16 3-pass.
//   per b: D[o, hw] = sum_c pw[o,c] * tmp[c,hw]
//   Block 128x128, 8 warps (2m x 4n), warp tile 64x32, K chunks of 32.
//   A: [m][k] bf16 smem, 80B padded rows (ldmatrix conflict-free).
//   B: fp32 coalesced load -> hi/lo bf16 -> smem [k][n] with 16B XOR swizzle
//      -> ldmatrix.x4.trans (conflict-free).
//   3 passes: Ah*Bh + Ah*Bl + Al*Bh, fp32 accumulate.
// ---------------------------------------------------------------------------
__global__ void __launch_bounds__(256) pw_gemm_mma(float* __restrict__ out) {
    // smem layout (bytes): A_hi[128*80]=10240 @0, A_lo @10240,
    //                      B_hi[32*256]=8192 @20480, B_lo @28672. total 36864
    __shared__ __align__(128) char sm[36864];
    const uint32_t smb = smem_u32(sm);
    const uint32_t aHi = smb, aLo = smb + 10240;
    const uint32_t bHi = smb + 20480, bLo = smb + 28672;

    const int tid = threadIdx.x;
    const int wid = tid >> 5, lane = tid & 31;
    const int warp_m = wid & 1;        // 0..1  -> m offset 0/64
    const int warp_n = wid >> 1;       // 0..3  -> n offset 0/32/64/96
    const int n0 = blockIdx.x * 128;
    const int m0 = blockIdx.y * 128;
    const int b  = blockIdx.z;

    float acc[4][4][4];                // [mi][ni][frag]
    #pragma unroll
    for (int i = 0; i < 4; i++)
        #pragma unroll
        for (int j = 0; j < 4; j++)
            #pragma unroll
            for (int q = 0; q < 4; q++) acc[i][j][q] = 0.f;

    // precomputed ldmatrix lane addresses (byte offsets, chunk-invariant parts)
    const int lm16 = lane & 15, lhi = lane >> 4;
    // A: row = warp_m*64 + mi*16 + lm16 ; colbyte = ks*32 + lhi*16
    const uint32_t aRowOff = (uint32_t)(warp_m * 64 + lm16) * 80 + (uint32_t)lhi * 16;
    // B: k = ks*16 + lm16 ; n = warp_n*32 + p*16 + lhi*8
    const int bN = warp_n * 32 + lhi * 8;  // + p*16

    const float* tb = g_tmp + (size_t)b * 1048576 + n0;
    float* ob = out + (size_t)b * 1048576;

    for (int kc = 0; kc < 8; kc++) {
        __syncthreads();   // previous chunk's ldmatrix reads complete

        // ---- load A hi/lo: per half 1024 x 8B ----
        #pragma unroll
        for (int half = 0; half < 2; half++) {
            const __nv_bfloat16* src = (half ? g_pw_lo : g_pw_hi) + (size_t)m0 * 256 + kc * 32;
            uint32_t dst = half ? aLo : aHi;
            #pragma unroll
            for (int i = 0; i < 4; i++) {
                int lin = tid + i * 256;        // 0..1023
                int r = lin >> 3, j = lin & 7;  // row, 8B chunk (4 bf16)
                uint2 v = *(const uint2*)(src + (size_t)r * 256 + j * 4);
                *(uint2*)(sm + (dst - smb) + r * 80 + j * 8) = v;
            }
        }

        // ---- load B fp32, split, swizzled STS ----
        {
            const float* tbc = tb + (size_t)kc * 32 * 4096;
            #pragma unroll
            for (int i = 0; i < 4; i++) {
                int lin = tid + i * 256;        // 0..1023
                int k = lin >> 5;               // 0..31
                int j = lin & 31;               // float4 idx along n (128 floats)
                float4 v = *(const float4*)(tbc + (size_t)k * 4096 + j * 4);
                __nv_bfloat16 h0 = __float2bfloat16(v.x), h1 = __float2bfloat16(v.y),
                              h2 = __float2bfloat16(v.z), h3 = __float2bfloat16(v.w);
                __nv_bfloat16 l0 = __float2bfloat16(v.x - __bfloat162float(h0)),
                              l1 = __float2bfloat16(v.y - __bfloat162float(h1)),
                              l2 = __float2bfloat16(v.z - __bfloat162float(h2)),
                              l3 = __float2bfloat16(v.w - __bfloat162float(h3));
                uint32_t off = (uint32_t)k * 256
                             + (uint32_t)(((j >> 1) ^ (k & 7)) * 16) + (uint32_t)(j & 1) * 8;
                __nv_bfloat162 p0, p1;
                p0.x = h0; p0.y = h1; p1.x = h2; p1.y = h3;
                uint2 uh; uh.x = *(uint32_t*)&p0; uh.y = *(uint32_t*)&p1;
                p0.x = l0; p0.y = l1; p1.x = l2; p1.y = l3;
                uint2 ul; ul.x = *(uint32_t*)&p0; ul.y = *(uint32_t*)&p1;
                *(uint2*)(sm + (bHi - smb) + off) = uh;
                *(uint2*)(sm + (bLo - smb) + off) = ul;
            }
        }
        __syncthreads();

        // ---- compute: 2 k16 steps x 3 passes ----
        #pragma unroll
        for (int ks = 0; ks < 2; ks++) {
            #pragma unroll
            for (int pass = 0; pass < 3; pass++) {
                const uint32_t aBase = (pass == 2) ? aLo : aHi;
                const uint32_t bBase = (pass == 1) ? bLo : bHi;

                uint32_t af[4][4];
                #pragma unroll
                for (int mi = 0; mi < 4; mi++)
                    ldsm_x4(af[mi], aBase + aRowOff + (uint32_t)mi * (16 * 80)
                                   + (uint32_t)ks * 32);

                uint32_t bf[2][4];
                #pragma unroll
                for (int p = 0; p < 2; p++) {
                    int k = ks * 16 + lm16;
                    int n = bN + p * 16;
                    uint32_t off = (uint32_t)k * 256
                                 + (uint32_t)(((n >> 3) ^ (k & 7)) * 16);
                    ldsm_x4_t(bf[p], bBase + off);
                }

                #pragma unroll
                for (int mi = 0; mi < 4; mi++) {
                    #pragma unroll
                    for (int p = 0; p < 2; p++) {
                        mma_bf16(acc[mi][2 * p],     af[mi], &bf[p][0]);
                        mma_bf16(acc[mi][2 * p + 1], af[mi], &bf[p][2]);
                    }
                }
            }
        }
    }

    // ---- epilogue: c0,c1 at (row, col), c2,c3 at (row+8, col) ----
    const int rowBase = m0 + warp_m * 64 + (lane >> 2);
    const int colBase = n0 + warp_n * 32 + (lane & 3) * 2;
    #pragma unroll
    for (int mi = 0; mi < 4; mi++) {
        #pragma unroll
        for (int ni = 0; ni < 4; ni++) {
            int r = rowBase + mi * 16;
            int c = colBase + ni * 8;
            float2 v0 = make_float2(acc[mi][ni][0], acc[mi][ni][1]);
            float2 v1 = make_float2(acc[mi][ni][2], acc[mi][ni][3]);
            *(float2*)&ob[(size_t)r * 4096 + c]       = v0;
            *(float2*)&ob[(size_t)(r + 8) * 4096 + c] = v1;
        }
    }
}

// ---------------------------------------------------------------------------
// launch
// ---------------------------------------------------------------------------
extern "C" void kernel_launch(void* const* d_in, const int* in_sizes, int n_in,
                              void* d_out, int out_size) {
    const float* x   = (const float*)d_in[0];  // [16,256,64,64]
    const float* dw  = (const float*)d_in[1];  // [256,1,7,7]
    const float* pwm = (const float*)d_in[2];  // [256,256]
    const float* w1  = (const float*)d_in[3];  // [64,256]
    const float* b1  = (const float*)d_in[4];  // [64]
    const float* w2  = (const float*)d_in[5];  // [12544,64]
    const float* b2  = (const float*)d_in[6];  // [12544]
    float* out = (float*)d_out;                // [16,256,64,64] fp32

    pw_split<<<256, 256>>>(pwm);
    pool_kernel<<<4096, 256>>>(x);
    mlp1_kernel<<<16, 64>>>(w1, b1);
    fuse_kernel<<<784, 256>>>(dw, w2, b2);
    dw_kernel<<<dim3(4, 4096), 256>>>(x);
    pw_gemm_mma<<<dim3(32, 2, 16), 256>>>(out);
}

// round 6
// speedup vs baseline: 1.5063x; 1.2843x over previous
#include <cuda_runtime.h>
#include <cuda_bf16.h>
#include <math.h>
#include <stdint.h>

#define DINLINE __device__ __forceinline__

// Problem constants: B=16, C=256, H=W=64, K=7, C/4=64, C*K*K=12544

// ---- scratch (static device allocations: allowed) ----
__device__ __align__(128) float g_pooled[16 * 256];            // [B, C]
__device__ __align__(128) float g_h[16 * 64];                  // [B, C/4]
__device__ __align__(128) float g_fused[16 * 256 * 49];        // [B, C, 49]
__device__ __align__(128) float g_tmp[16u * 256u * 64u * 64u]; // [B, C, H, W] depthwise out
__device__ __align__(128) __nv_bfloat16 g_pw_hi[256 * 256];    // bf16 hi split of pw
__device__ __align__(128) __nv_bfloat16 g_pw_lo[256 * 256];    // bf16 lo split of pw

// ===========================================================================
// sm_80-era PTX helpers (legal on plain sm_100 target)
// ===========================================================================
DINLINE uint32_t smem_u32(const void* p) {
    uint32_t a;
    asm("{ .reg .u64 t; cvta.to.shared.u64 t, %1; cvt.u32.u64 %0, t; }" : "=r"(a) : "l"(p));
    return a;
}
DINLINE void ldsm_x4(uint32_t* r, uint32_t addr) {
    asm volatile("ldmatrix.sync.aligned.m8n8.x4.shared.b16 {%0,%1,%2,%3}, [%4];"
                 : "=r"(r[0]), "=r"(r[1]), "=r"(r[2]), "=r"(r[3]) : "r"(addr));
}
DINLINE void ldsm_x4_t(uint32_t* r, uint32_t addr) {
    asm volatile("ldmatrix.sync.aligned.m8n8.x4.trans.shared.b16 {%0,%1,%2,%3}, [%4];"
                 : "=r"(r[0]), "=r"(r[1]), "=r"(r[2]), "=r"(r[3]) : "r"(addr));
}
DINLINE void mma_bf16(float* d, const uint32_t* a, const uint32_t* b) {
    asm volatile(
        "mma.sync.aligned.m16n8k16.row.col.f32.bf16.bf16.f32 "
        "{%0,%1,%2,%3}, {%4,%5,%6,%7}, {%8,%9}, {%0,%1,%2,%3};"
        : "+f"(d[0]), "+f"(d[1]), "+f"(d[2]), "+f"(d[3])
        : "r"(a[0]), "r"(a[1]), "r"(a[2]), "r"(a[3]), "r"(b[0]), "r"(b[1]));
}
DINLINE void cp16(uint32_t dst, const void* src) {
    asm volatile("cp.async.cg.shared.global [%0], [%1], 16;"
                 :: "r"(dst), "l"(__cvta_generic_to_global(src)));
}
DINLINE void cp_commit() { asm volatile("cp.async.commit_group;" ::: "memory"); }
DINLINE void cp_wait0()  { asm volatile("cp.async.wait_group 0;" ::: "memory"); }

// ---------------------------------------------------------------------------
// Kernel 0: split pw weights into bf16 hi/lo
// ---------------------------------------------------------------------------
__global__ void pw_split(const float* __restrict__ pw) {
    int i = blockIdx.x * 256 + threadIdx.x;   // 65536 elems
    float v = pw[i];
    __nv_bfloat16 h = __float2bfloat16(v);
    g_pw_hi[i] = h;
    g_pw_lo[i] = __float2bfloat16(v - __bfloat162float(h));
}

// ---------------------------------------------------------------------------
// Kernel 1: global average pool
// ---------------------------------------------------------------------------
__global__ void pool_kernel(const float* __restrict__ x) {
    int bc = blockIdx.x;
    const float4* xp = (const float4*)(x + (size_t)bc * 4096);
    float s = 0.f;
    #pragma unroll 4
    for (int i = threadIdx.x; i < 1024; i += 256) {
        float4 v = xp[i];
        s += (v.x + v.y) + (v.z + v.w);
    }
    __shared__ float red[256];
    red[threadIdx.x] = s;
    __syncthreads();
    for (int off = 128; off > 0; off >>= 1) {
        if (threadIdx.x < off) red[threadIdx.x] += red[threadIdx.x + off];
        __syncthreads();
    }
    if (threadIdx.x == 0) g_pooled[bc] = red[0] * (1.f / 4096.f);
}

// ---------------------------------------------------------------------------
// Kernel 2: h = gelu(pooled @ w1^T + b1)
// ---------------------------------------------------------------------------
__global__ void mlp1_kernel(const float* __restrict__ w1, const float* __restrict__ b1) {
    int b = blockIdx.x;
    int j = threadIdx.x;   // 0..63
    __shared__ float p[256];
    for (int i = threadIdx.x; i < 256; i += 64) p[i] = g_pooled[b * 256 + i];
    __syncthreads();
    float s = b1[j];
    const float* wr = w1 + (size_t)j * 256;
    #pragma unroll 8
    for (int c = 0; c < 256; c++) s += p[c] * wr[c];
    g_h[b * 64 + j] = 0.5f * s * (1.0f + erff(s * 0.70710678118654752f));
}

// ---------------------------------------------------------------------------
// Kernel 3 v2: fused[b,wi] = dw[wi] + b2[wi] + sum_j h[b,j]*w2[wi,j]
// Tiny GEMM: coalesced w2 tile in smem (read ONCE, reused for all 16 b).
// grid = 98 blocks x 256 threads; each thread: 1 wi x 8 b.
// ---------------------------------------------------------------------------
__global__ void __launch_bounds__(256) fuse_kernel(const float* __restrict__ dw,
                                                   const float* __restrict__ w2,
                                                   const float* __restrict__ b2) {
    __shared__ float hs[16 * 64];      // [b][j]
    __shared__ float w2s[128 * 68];    // 128 rows, padded to 68 floats
    int tid = threadIdx.x;
    int wi0 = blockIdx.x * 128;

    // load all of h (1024 floats)
    *(float4*)(hs + tid * 4) = *(const float4*)(g_h + tid * 4);
    // load w2 tile [128][64], coalesced
    #pragma unroll
    for (int i = 0; i < 8; i++) {
        int lin = tid + i * 256;        // float4 units, 0..2047
        int r = lin >> 4, j4 = lin & 15;
        float4 v = *(const float4*)(w2 + (size_t)(wi0 + r) * 64 + j4 * 4);
        *(float4*)(w2s + r * 68 + j4 * 4) = v;
    }
    __syncthreads();

    int wiL = tid & 127;
    int bg = (tid >> 7) * 8;            // 0 or 8
    int wi = wi0 + wiL;
    float base = dw[wi] + b2[wi];
    float acc[8];
    #pragma unroll
    for (int bb = 0; bb < 8; bb++) acc[bb] = base;

    const float* wr = w2s + wiL * 68;
    #pragma unroll
    for (int j4 = 0; j4 < 16; j4++) {
        float4 w = *(const float4*)(wr + j4 * 4);
        #pragma unroll
        for (int bb = 0; bb < 8; bb++) {
            float4 h = *(const float4*)(hs + (bg + bb) * 64 + j4 * 4);
            acc[bb] += w.x * h.x + w.y * h.y + w.z * h.z + w.w * h.w;
        }
    }
    #pragma unroll
    for (int bb = 0; bb < 8; bb++)
        g_fused[(size_t)(bg + bb) * 12544 + wi] = acc[bb];
}

// ---------------------------------------------------------------------------
// Kernel 4: per-sample depthwise 7x7 conv, pad=3.  4 rows/thread,
// weights pinned into registers via asm barrier.
// ---------------------------------------------------------------------------
__global__ void __launch_bounds__(256, 2) dw_kernel(const float* __restrict__ x) {
    int bc = blockIdx.y;
    int rowBase = blockIdx.x * 16;
    const float* xp = x + (size_t)bc * 4096;

    __shared__ float s[22 * 70];
    __shared__ float wsh[49];

    if (threadIdx.x < 49) wsh[threadIdx.x] = g_fused[bc * 49 + threadIdx.x];

    for (int i = threadIdx.x; i < 22 * 70; i += 256) {
        int r = i / 70, cc = i - r * 70;
        int gr = rowBase + r - 3, gc = cc - 3;
        s[i] = (gr >= 0 && gr < 64 && gc >= 0 && gc < 64) ? xp[gr * 64 + gc] : 0.f;
    }
    __syncthreads();

    float w[49];
    #pragma unroll
    for (int q = 0; q < 49; q++) w[q] = wsh[q];
    #pragma unroll
    for (int q = 0; q < 49; q++) asm volatile("" : "+f"(w[q]));

    int col = threadIdx.x & 63;
    int lr0 = (threadIdx.x >> 6) * 4;

    float acc[4] = {0.f, 0.f, 0.f, 0.f};
    #pragma unroll
    for (int r = 0; r < 10; r++) {
        float v[7];
        #pragma unroll
        for (int kx = 0; kx < 7; kx++) v[kx] = s[(lr0 + r) * 70 + col + kx];
        #pragma unroll
        for (int i = 0; i < 4; i++) {
            int ky = r - i;
            if (ky >= 0 && ky < 7) {
                #pragma unroll
                for (int kx = 0; kx < 7; kx++) acc[i] += v[kx] * w[ky * 7 + kx];
            }
        }
    }
    #pragma unroll
    for (int i = 0; i < 4; i++) {
        g_tmp[(size_t)bc * 4096 + (rowBase + lr0 + i) * 64 + col] = acc[i];
    }
}

// ---------------------------------------------------------------------------
// Kernel 5: pointwise GEMM via mma.sync bf16 3-pass, 2-stage pipelined.
//   Stage layout (36864 B each): A_hi[128x80B] @0, A_lo @10240,
//                                B_hi[32x256B] @20480, B_lo @28672
//   A via cp.async (bf16 pre-split), B fp32 LDG->reg prefetch->split->STS.
// ---------------------------------------------------------------------------
__global__ void __launch_bounds__(256) pw_gemm_mma(float* __restrict__ out) {
    extern __shared__ __align__(128) char sm[];
    const uint32_t smb = smem_u32(sm);

    const int tid = threadIdx.x;
    const int wid = tid >> 5, lane = tid & 31;
    const int warp_m = wid & 1;
    const int warp_n = wid >> 1;
    const int n0 = blockIdx.x * 128;
    const int m0 = blockIdx.y * 128;
    const int b  = blockIdx.z;

    float acc[4][4][4];
    #pragma unroll
    for (int i = 0; i < 4; i++)
        #pragma unroll
        for (int j = 0; j < 4; j++)
            #pragma unroll
            for (int q = 0; q < 4; q++) acc[i][j][q] = 0.f;

    const int lm16 = lane & 15, lhi = lane >> 4;
    const uint32_t aRowOff = (uint32_t)(warp_m * 64 + lm16) * 80 + (uint32_t)lhi * 16;
    const int bN = warp_n * 32 + lhi * 8;

    const float* tb = g_tmp + (size_t)b * 1048576 + n0;
    float* ob = out + (size_t)b * 1048576;

    // per-thread load indices
    const int bK = tid >> 5;            // base k row for B loads (0..31 via lin)
    (void)bK;

    // ---- A cp.async issue: 1024 x 16B chunks per chunk kc ----
    auto issueA = [&](int kc, uint32_t sbase) {
        #pragma unroll
        for (int i = 0; i < 4; i++) {
            int lin = tid + i * 256;            // 0..1023
            int half = lin >> 9;                // 0=hi,1=lo
            int c = lin & 511;
            int r = c >> 2, j = c & 3;          // row 0..127, 16B chunk 0..3
            const __nv_bfloat16* src =
                (half ? g_pw_lo : g_pw_hi) + (size_t)(m0 + r) * 256 + kc * 32 + j * 8;
            cp16(sbase + half * 10240 + r * 80 + j * 16, src);
        }
        cp_commit();
    };

    // ---- B global loads into regs ----
    float4 bpf[4];
    auto ldgB = [&](int kc) {
        const float* tbc = tb + (size_t)kc * 32 * 4096;
        #pragma unroll
        for (int i = 0; i < 4; i++) {
            int lin = tid + i * 256;
            int k = lin >> 5, j = lin & 31;
            bpf[i] = *(const float4*)(tbc + (size_t)k * 4096 + j * 4);
        }
    };
    // ---- B split + swizzled STS ----
    auto stsB = [&](uint32_t sbase) {
        #pragma unroll
        for (int i = 0; i < 4; i++) {
            int lin = tid + i * 256;
            int k = lin >> 5, j = lin & 31;
            float4 v = bpf[i];
            __nv_bfloat16 h0 = __float2bfloat16(v.x), h1 = __float2bfloat16(v.y),
                          h2 = __float2bfloat16(v.z), h3 = __float2bfloat16(v.w);
            __nv_bfloat16 l0 = __float2bfloat16(v.x - __bfloat162float(h0)),
                          l1 = __float2bfloat16(v.y - __bfloat162float(h1)),
                          l2 = __float2bfloat16(v.z - __bfloat162float(h2)),
                          l3 = __float2bfloat16(v.w - __bfloat162float(h3));
            uint32_t off = (uint32_t)k * 256
                         + (uint32_t)(((j >> 1) ^ (k & 7)) * 16) + (uint32_t)(j & 1) * 8;
            __nv_bfloat162 p0, p1;
            p0.x = h0; p0.y = h1; p1.x = h2; p1.y = h3;
            uint2 uh; uh.x = *(uint32_t*)&p0; uh.y = *(uint32_t*)&p1;
            p0.x = l0; p0.y = l1; p1.x = l2; p1.y = l3;
            uint2 ul; ul.x = *(uint32_t*)&p0; ul.y = *(uint32_t*)&p1;
            *(uint2*)(sm + (sbase - smb) + 20480 + off) = uh;
            *(uint2*)(sm + (sbase - smb) + 28672 + off) = ul;
        }
    };

    // ---- prologue ----
    ldgB(0);
    issueA(0, smb);

    for (int kc = 0; kc < 8; kc++) {
        const uint32_t sbase = smb + (uint32_t)(kc & 1) * 36864;
        cp_wait0();
        __syncthreads();                 // A(kc) visible; compute(kc-1) done; stage free
        stsB(sbase);
        if (kc < 7) {
            ldgB(kc + 1);                // latency hidden under compute
            issueA(kc + 1, smb + (uint32_t)((kc + 1) & 1) * 36864);
        }
        __syncthreads();                 // B STS visible

        const uint32_t aHi = sbase, aLo = sbase + 10240;
        const uint32_t bHi = sbase + 20480, bLo = sbase + 28672;
        #pragma unroll
        for (int ks = 0; ks < 2; ks++) {
            #pragma unroll
            for (int pass = 0; pass < 3; pass++) {
                const uint32_t aBase = (pass == 2) ? aLo : aHi;
                const uint32_t bBase = (pass == 1) ? bLo : bHi;

                uint32_t af[4][4];
                #pragma unroll
                for (int mi = 0; mi < 4; mi++)
                    ldsm_x4(af[mi], aBase + aRowOff + (uint32_t)mi * (16 * 80)
                                   + (uint32_t)ks * 32);

                uint32_t bf[2][4];
                #pragma unroll
                for (int p = 0; p < 2; p++) {
                    int k = ks * 16 + lm16;
                    int n = bN + p * 16;
                    uint32_t off = (uint32_t)k * 256
                                 + (uint32_t)(((n >> 3) ^ (k & 7)) * 16);
                    ldsm_x4_t(bf[p], bBase + off);
                }

                #pragma unroll
                for (int mi = 0; mi < 4; mi++) {
                    #pragma unroll
                    for (int p = 0; p < 2; p++) {
                        mma_bf16(acc[mi][2 * p],     af[mi], &bf[p][0]);
                        mma_bf16(acc[mi][2 * p + 1], af[mi], &bf[p][2]);
                    }
                }
            }
        }
    }

    // ---- epilogue ----
    const int rowBase = m0 + warp_m * 64 + (lane >> 2);
    const int colBase = n0 + warp_n * 32 + (lane & 3) * 2;
    #pragma unroll
    for (int mi = 0; mi < 4; mi++) {
        #pragma unroll
        for (int ni = 0; ni < 4; ni++) {
            int r = rowBase + mi * 16;
            int c = colBase + ni * 8;
            *(float2*)&ob[(size_t)r * 4096 + c] =
                make_float2(acc[mi][ni][0], acc[mi][ni][1]);
            *(float2*)&ob[(size_t)(r + 8) * 4096 + c] =
                make_float2(acc[mi][ni][2], acc[mi][ni][3]);
        }
    }
}

// ---------------------------------------------------------------------------
// launch
// ---------------------------------------------------------------------------
extern "C" void kernel_launch(void* const* d_in, const int* in_sizes, int n_in,
                              void* d_out, int out_size) {
    const float* x   = (const float*)d_in[0];  // [16,256,64,64]
    const float* dw  = (const float*)d_in[1];  // [256,1,7,7]
    const float* pwm = (const float*)d_in[2];  // [256,256]
    const float* w1  = (const float*)d_in[3];  // [64,256]
    const float* b1  = (const float*)d_in[4];  // [64]
    const float* w2  = (const float*)d_in[5];  // [12544,64]
    const float* b2  = (const float*)d_in[6];  // [12544]
    float* out = (float*)d_out;                // [16,256,64,64] fp32

    // idempotent, called every launch (no static guards allowed)
    cudaFuncSetAttribute(pw_gemm_mma, cudaFuncAttributeMaxDynamicSharedMemorySize, 73728);

    pw_split<<<256, 256>>>(pwm);
    pool_kernel<<<4096, 256>>>(x);
    mlp1_kernel<<<16, 64>>>(w1, b1);
    fuse_kernel<<<98, 256>>>(dw, w2, b2);
    dw_kernel<<<dim3(4, 4096), 256>>>(x);
    pw_gemm_mma<<<dim3(32, 2, 16), 256, 73728>>>(out);
}

// round 7
// speedup vs baseline: 1.7865x; 1.1860x over previous
#include <cuda_runtime.h>
#include <cuda_bf16.h>
#include <math.h>
#include <stdint.h>

#define DINLINE __device__ __forceinline__

// Problem constants: B=16, C=256, H=W=64, K=7, C/4=64, C*K*K=12544

// ---- scratch (static device allocations: allowed) ----
__device__ __align__(128) float g_pooled[16 * 256];            // [B, C]
__device__ __align__(128) float g_h[16 * 64];                  // [B, C/4]
__device__ __align__(128) float g_fused[16 * 256 * 49];        // [B, C, 49]
__device__ __align__(128) __nv_bfloat16 g_bhi[16u*256u*64u*64u]; // dw out, bf16 hi
__device__ __align__(128) __nv_bfloat16 g_blo[16u*256u*64u*64u]; // dw out, bf16 lo
__device__ __align__(128) __nv_bfloat16 g_pw_hi[256 * 256];    // bf16 hi split of pw
__device__ __align__(128) __nv_bfloat16 g_pw_lo[256 * 256];    // bf16 lo split of pw

// ===========================================================================
// sm_80-era PTX helpers (legal on plain sm_100 target)
// ===========================================================================
DINLINE uint32_t smem_u32(const void* p) {
    uint32_t a;
    asm("{ .reg .u64 t; cvta.to.shared.u64 t, %1; cvt.u32.u64 %0, t; }" : "=r"(a) : "l"(p));
    return a;
}
DINLINE void ldsm_x4(uint32_t* r, uint32_t addr) {
    asm volatile("ldmatrix.sync.aligned.m8n8.x4.shared.b16 {%0,%1,%2,%3}, [%4];"
                 : "=r"(r[0]), "=r"(r[1]), "=r"(r[2]), "=r"(r[3]) : "r"(addr));
}
DINLINE void ldsm_x4_t(uint32_t* r, uint32_t addr) {
    asm volatile("ldmatrix.sync.aligned.m8n8.x4.trans.shared.b16 {%0,%1,%2,%3}, [%4];"
                 : "=r"(r[0]), "=r"(r[1]), "=r"(r[2]), "=r"(r[3]) : "r"(addr));
}
DINLINE void mma_bf16(float* d, const uint32_t* a, const uint32_t* b) {
    asm volatile(
        "mma.sync.aligned.m16n8k16.row.col.f32.bf16.bf16.f32 "
        "{%0,%1,%2,%3}, {%4,%5,%6,%7}, {%8,%9}, {%0,%1,%2,%3};"
        : "+f"(d[0]), "+f"(d[1]), "+f"(d[2]), "+f"(d[3])
        : "r"(a[0]), "r"(a[1]), "r"(a[2]), "r"(a[3]), "r"(b[0]), "r"(b[1]));
}
DINLINE void cp16(uint32_t dst, const void* src) {
    asm volatile("cp.async.cg.shared.global [%0], [%1], 16;"
                 :: "r"(dst), "l"(__cvta_generic_to_global(src)));
}
DINLINE void cp_commit() { asm volatile("cp.async.commit_group;" ::: "memory"); }
DINLINE void cp_wait0()  { asm volatile("cp.async.wait_group 0;" ::: "memory"); }
DINLINE void cp_wait1()  { asm volatile("cp.async.wait_group 1;" ::: "memory"); }

// ---------------------------------------------------------------------------
// Kernel 0: split pw weights into bf16 hi/lo
// ---------------------------------------------------------------------------
__global__ void pw_split(const float* __restrict__ pw) {
    int i = blockIdx.x * 256 + threadIdx.x;   // 65536 elems
    float v = pw[i];
    __nv_bfloat16 h = __float2bfloat16(v);
    g_pw_hi[i] = h;
    g_pw_lo[i] = __float2bfloat16(v - __bfloat162float(h));
}

// ---------------------------------------------------------------------------
// Kernel 1: global average pool
// ---------------------------------------------------------------------------
__global__ void pool_kernel(const float* __restrict__ x) {
    int bc = blockIdx.x;
    const float4* xp = (const float4*)(x + (size_t)bc * 4096);
    float s = 0.f;
    #pragma unroll 4
    for (int i = threadIdx.x; i < 1024; i += 256) {
        float4 v = xp[i];
        s += (v.x + v.y) + (v.z + v.w);
    }
    __shared__ float red[256];
    red[threadIdx.x] = s;
    __syncthreads();
    for (int off = 128; off > 0; off >>= 1) {
        if (threadIdx.x < off) red[threadIdx.x] += red[threadIdx.x + off];
        __syncthreads();
    }
    if (threadIdx.x == 0) g_pooled[bc] = red[0] * (1.f / 4096.f);
}

// ---------------------------------------------------------------------------
// Kernel 2: h = gelu(pooled @ w1^T + b1)
// ---------------------------------------------------------------------------
__global__ void mlp1_kernel(const float* __restrict__ w1, const float* __restrict__ b1) {
    int b = blockIdx.x;
    int j = threadIdx.x;   // 0..63
    __shared__ float p[256];
    for (int i = threadIdx.x; i < 256; i += 64) p[i] = g_pooled[b * 256 + i];
    __syncthreads();
    float s = b1[j];
    const float* wr = w1 + (size_t)j * 256;
    #pragma unroll 8
    for (int c = 0; c < 256; c++) s += p[c] * wr[c];
    g_h[b * 64 + j] = 0.5f * s * (1.0f + erff(s * 0.70710678118654752f));
}

// ---------------------------------------------------------------------------
// Kernel 3: fused[b,wi] = dw[wi] + b2[wi] + sum_j h[b,j]*w2[wi,j]
// coalesced w2 tile in smem, reused for all 16 b.
// ---------------------------------------------------------------------------
__global__ void __launch_bounds__(256) fuse_kernel(const float* __restrict__ dw,
                                                   const float* __restrict__ w2,
                                                   const float* __restrict__ b2) {
    __shared__ float hs[16 * 64];
    __shared__ float w2s[128 * 68];
    int tid = threadIdx.x;
    int wi0 = blockIdx.x * 128;

    *(float4*)(hs + tid * 4) = *(const float4*)(g_h + tid * 4);
    #pragma unroll
    for (int i = 0; i < 8; i++) {
        int lin = tid + i * 256;
        int r = lin >> 4, j4 = lin & 15;
        float4 v = *(const float4*)(w2 + (size_t)(wi0 + r) * 64 + j4 * 4);
        *(float4*)(w2s + r * 68 + j4 * 4) = v;
    }
    __syncthreads();

    int wiL = tid & 127;
    int bg = (tid >> 7) * 8;
    int wi = wi0 + wiL;
    float base = dw[wi] + b2[wi];
    float acc[8];
    #pragma unroll
    for (int bb = 0; bb < 8; bb++) acc[bb] = base;

    const float* wr = w2s + wiL * 68;
    #pragma unroll
    for (int j4 = 0; j4 < 16; j4++) {
        float4 w = *(const float4*)(wr + j4 * 4);
        #pragma unroll
        for (int bb = 0; bb < 8; bb++) {
            float4 h = *(const float4*)(hs + (bg + bb) * 64 + j4 * 4);
            acc[bb] += w.x * h.x + w.y * h.y + w.z * h.z + w.w * h.w;
        }
    }
    #pragma unroll
    for (int bb = 0; bb < 8; bb++)
        g_fused[(size_t)(bg + bb) * 12544 + wi] = acc[bb];
}

// ---------------------------------------------------------------------------
// Kernel 4: per-sample depthwise 7x7 conv, pad=3.
// Thread = 2 cols x 2 rows; epilogue converts to bf16 hi/lo and stores
// packed uint32 (coalesced 128B per warp per row per half).
// ---------------------------------------------------------------------------
__global__ void __launch_bounds__(256, 2) dw_kernel(const float* __restrict__ x) {
    int bc = blockIdx.y;
    int rowBase = blockIdx.x * 16;
    const float* xp = x + (size_t)bc * 4096;

    __shared__ __align__(16) float s[22 * 70];
    __shared__ float wsh[49];

    if (threadIdx.x < 49) wsh[threadIdx.x] = g_fused[bc * 49 + threadIdx.x];

    for (int i = threadIdx.x; i < 22 * 70; i += 256) {
        int r = i / 70, cc = i - r * 70;
        int gr = rowBase + r - 3, gc = cc - 3;
        s[i] = (gr >= 0 && gr < 64 && gc >= 0 && gc < 64) ? xp[gr * 64 + gc] : 0.f;
    }
    __syncthreads();

    float w[49];
    #pragma unroll
    for (int q = 0; q < 49; q++) w[q] = wsh[q];
    #pragma unroll
    for (int q = 0; q < 49; q++) asm volatile("" : "+f"(w[q]));

    int c0  = (threadIdx.x & 31) * 2;   // output cols c0, c0+1
    int lr0 = (threadIdx.x >> 5) * 2;   // local output rows lr0, lr0+1

    float acc[2][2] = {{0.f, 0.f}, {0.f, 0.f}};
    #pragma unroll
    for (int r = 0; r < 8; r++) {       // smem rows lr0 .. lr0+7
        float v[8];
        const float* row = s + (lr0 + r) * 70 + c0;
        #pragma unroll
        for (int q = 0; q < 4; q++) *(float2*)&v[q * 2] = *(const float2*)(row + q * 2);
        #pragma unroll
        for (int dy = 0; dy < 2; dy++) {
            int ky = r - dy;
            if (ky >= 0 && ky < 7) {
                #pragma unroll
                for (int kx = 0; kx < 7; kx++) {
                    float wv = w[ky * 7 + kx];
                    acc[dy][0] += v[kx] * wv;
                    acc[dy][1] += v[kx + 1] * wv;
                }
            }
        }
    }

    #pragma unroll
    for (int dy = 0; dy < 2; dy++) {
        int row = rowBase + lr0 + dy;
        uint32_t idx = (uint32_t)bc * 4096u + (uint32_t)row * 64u + (uint32_t)c0;
        __nv_bfloat162 hp, lp;
        hp.x = __float2bfloat16(acc[dy][0]);
        hp.y = __float2bfloat16(acc[dy][1]);
        lp.x = __float2bfloat16(acc[dy][0] - __bfloat162float(hp.x));
        lp.y = __float2bfloat16(acc[dy][1] - __bfloat162float(hp.y));
        *(uint32_t*)&g_bhi[idx] = *(uint32_t*)&hp;
        *(uint32_t*)&g_blo[idx] = *(uint32_t*)&lp;
    }
}

// ---------------------------------------------------------------------------
// Kernel 5: pointwise GEMM via mma.sync bf16 3-pass, 3-stage cp.async pipeline.
//   Stage (36864 B): A_hi[128x80B] @0, A_lo @10240, B_hi[32x256B] @20480,
//   B_lo @28672.  Both A and B arrive pre-split in bf16 -> pure cp.async,
//   one __syncthreads per chunk.
// ---------------------------------------------------------------------------
__global__ void __launch_bounds__(256) pw_gemm_mma(float* __restrict__ out) {
    extern __shared__ __align__(128) char sm[];
    const uint32_t smb = smem_u32(sm);

    const int tid = threadIdx.x;
    const int wid = tid >> 5, lane = tid & 31;
    const int warp_m = wid & 1;
    const int warp_n = wid >> 1;
    const int n0 = blockIdx.x * 128;
    const int m0 = blockIdx.y * 128;
    const int b  = blockIdx.z;

    float acc[4][4][4];
    #pragma unroll
    for (int i = 0; i < 4; i++)
        #pragma unroll
        for (int j = 0; j < 4; j++)
            #pragma unroll
            for (int q = 0; q < 4; q++) acc[i][j][q] = 0.f;

    const int lm16 = lane & 15, lhi = lane >> 4;
    const uint32_t aRowOff = (uint32_t)(warp_m * 64 + lm16) * 80 + (uint32_t)lhi * 16;
    const int bN = warp_n * 32 + lhi * 8;

    float* ob = out + (size_t)b * 1048576;

    // per-thread cp.async indices (chunk-invariant)
    const int aHalf = tid >> 9;  // unused directly; lin-based below
    (void)aHalf;

    auto issue = [&](int kc, uint32_t sbase) {
        // A: 1024 x 16B (2 halves x 128 rows x 4 chunks)
        #pragma unroll
        for (int i = 0; i < 4; i++) {
            int lin = tid + i * 256;
            int half = lin >> 9;
            int c = lin & 511;
            int r = c >> 2, j = c & 3;
            const __nv_bfloat16* src =
                (half ? g_pw_lo : g_pw_hi) + (size_t)(m0 + r) * 256 + kc * 32 + j * 8;
            cp16(sbase + half * 10240 + r * 80 + j * 16, src);
        }
        // B: 1024 x 16B (2 halves x 32 k-rows x 16 chunks), swizzled dst
        #pragma unroll
        for (int i = 0; i < 4; i++) {
            int lin = tid + i * 256;
            int half = lin >> 9;
            int c = lin & 511;
            int k = c >> 4, j16 = c & 15;
            const __nv_bfloat16* src =
                (half ? g_blo : g_bhi) + (size_t)b * 1048576
                + (size_t)(kc * 32 + k) * 4096 + n0 + j16 * 8;
            cp16(sbase + 20480 + half * 8192 + (uint32_t)k * 256
                 + (uint32_t)((j16 ^ (k & 7)) * 16), src);
        }
        cp_commit();
    };

    // prologue: fill 2 of 3 stages
    issue(0, smb);
    issue(1, smb + 36864);

    for (int kc = 0; kc < 8; kc++) {
        const uint32_t sbase = smb + (uint32_t)(kc % 3) * 36864;
        if (kc == 7) cp_wait0(); else cp_wait1();
        __syncthreads();                       // stage kc ready; compute(kc-1) done
        if (kc < 6) issue(kc + 2, smb + (uint32_t)((kc + 2) % 3) * 36864);

        const uint32_t aHi = sbase, aLo = sbase + 10240;
        const uint32_t bHi = sbase + 20480, bLo = sbase + 28672;
        #pragma unroll
        for (int ks = 0; ks < 2; ks++) {
            #pragma unroll
            for (int pass = 0; pass < 3; pass++) {
                const uint32_t aBase = (pass == 2) ? aLo : aHi;
                const uint32_t bBase = (pass == 1) ? bLo : bHi;

                uint32_t af[4][4];
                #pragma unroll
                for (int mi = 0; mi < 4; mi++)
                    ldsm_x4(af[mi], aBase + aRowOff + (uint32_t)mi * (16 * 80)
                                   + (uint32_t)ks * 32);

                uint32_t bf[2][4];
                #pragma unroll
                for (int p = 0; p < 2; p++) {
                    int k = ks * 16 + lm16;
                    int n = bN + p * 16;
                    uint32_t off = (uint32_t)k * 256
                                 + (uint32_t)(((n >> 3) ^ (k & 7)) * 16);
                    ldsm_x4_t(bf[p], bBase + off);
                }

                #pragma unroll
                for (int mi = 0; mi < 4; mi++) {
                    #pragma unroll
                    for (int p = 0; p < 2; p++) {
                        mma_bf16(acc[mi][2 * p],     af[mi], &bf[p][0]);
                        mma_bf16(acc[mi][2 * p + 1], af[mi], &bf[p][2]);
                    }
                }
            }
        }
    }

    // epilogue
    const int rowBase = m0 + warp_m * 64 + (lane >> 2);
    const int colBase = n0 + warp_n * 32 + (lane & 3) * 2;
    #pragma unroll
    for (int mi = 0; mi < 4; mi++) {
        #pragma unroll
        for (int ni = 0; ni < 4; ni++) {
            int r = rowBase + mi * 16;
            int c = colBase + ni * 8;
            *(float2*)&ob[(size_t)r * 4096 + c] =
                make_float2(acc[mi][ni][0], acc[mi][ni][1]);
            *(float2*)&ob[(size_t)(r + 8) * 4096 + c] =
                make_float2(acc[mi][ni][2], acc[mi][ni][3]);
        }
    }
}

// ---------------------------------------------------------------------------
// launch
// ---------------------------------------------------------------------------
extern "C" void kernel_launch(void* const* d_in, const int* in_sizes, int n_in,
                              void* d_out, int out_size) {
    const float* x   = (const float*)d_in[0];  // [16,256,64,64]
    const float* dw  = (const float*)d_in[1];  // [256,1,7,7]
    const float* pwm = (const float*)d_in[2];  // [256,256]
    const float* w1  = (const float*)d_in[3];  // [64,256]
    const float* b1  = (const float*)d_in[4];  // [64]
    const float* w2  = (const float*)d_in[5];  // [12544,64]
    const float* b2  = (const float*)d_in[6];  // [12544]
    float* out = (float*)d_out;                // [16,256,64,64] fp32

    cudaFuncSetAttribute(pw_gemm_mma, cudaFuncAttributeMaxDynamicSharedMemorySize, 110592);

    pw_split<<<256, 256>>>(pwm);
    pool_kernel<<<4096, 256>>>(x);
    mlp1_kernel<<<16, 64>>>(w1, b1);
    fuse_kernel<<<98, 256>>>(dw, w2, b2);
    dw_kernel<<<dim3(4, 4096), 256>>>(x);
    pw_gemm_mma<<<dim3(32, 2, 16), 256, 110592>>>(out);
}

// round 8
// speedup vs baseline: 1.9713x; 1.1034x over previous
#include <cuda_runtime.h>
#include <cuda_fp16.h>
#include <math.h>
#include <stdint.h>

#define DINLINE __device__ __forceinline__

// Problem constants: B=16, C=256, H=W=64, K=7, C/4=64, C*K*K=12544

// ---- scratch (static device allocations: allowed) ----
__device__ __align__(128) float g_pooled[16 * 256];            // [B, C]
__device__ __align__(128) float g_h[16 * 64];                  // [B, C/4]
__device__ __align__(128) float g_fused[16 * 256 * 49];        // [B, C, 49]
__device__ __align__(128) __half g_bh[16u*256u*64u*64u];       // dw out, fp16 (32 MB)
__device__ __align__(128) __half g_pw_hi[256 * 256];           // fp16 hi split of pw
__device__ __align__(128) __half g_pw_lo[256 * 256];           // fp16 lo split of pw

// ===========================================================================
// sm_80-era PTX helpers (legal on plain sm_100 target)
// ===========================================================================
DINLINE uint32_t smem_u32(const void* p) {
    uint32_t a;
    asm("{ .reg .u64 t; cvta.to.shared.u64 t, %1; cvt.u32.u64 %0, t; }" : "=r"(a) : "l"(p));
    return a;
}
DINLINE void ldsm_x4(uint32_t* r, uint32_t addr) {
    asm volatile("ldmatrix.sync.aligned.m8n8.x4.shared.b16 {%0,%1,%2,%3}, [%4];"
                 : "=r"(r[0]), "=r"(r[1]), "=r"(r[2]), "=r"(r[3]) : "r"(addr));
}
DINLINE void ldsm_x4_t(uint32_t* r, uint32_t addr) {
    asm volatile("ldmatrix.sync.aligned.m8n8.x4.trans.shared.b16 {%0,%1,%2,%3}, [%4];"
                 : "=r"(r[0]), "=r"(r[1]), "=r"(r[2]), "=r"(r[3]) : "r"(addr));
}
DINLINE void mma_f16(float* d, const uint32_t* a, const uint32_t* b) {
    asm volatile(
        "mma.sync.aligned.m16n8k16.row.col.f32.f16.f16.f32 "
        "{%0,%1,%2,%3}, {%4,%5,%6,%7}, {%8,%9}, {%0,%1,%2,%3};"
        : "+f"(d[0]), "+f"(d[1]), "+f"(d[2]), "+f"(d[3])
        : "r"(a[0]), "r"(a[1]), "r"(a[2]), "r"(a[3]), "r"(b[0]), "r"(b[1]));
}
DINLINE void cp16(uint32_t dst, const void* src) {
    asm volatile("cp.async.cg.shared.global [%0], [%1], 16;"
                 :: "r"(dst), "l"(__cvta_generic_to_global(src)));
}
DINLINE void cp_commit() { asm volatile("cp.async.commit_group;" ::: "memory"); }
DINLINE void cp_wait0()  { asm volatile("cp.async.wait_group 0;" ::: "memory"); }
DINLINE void cp_wait1()  { asm volatile("cp.async.wait_group 1;" ::: "memory"); }

// ---------------------------------------------------------------------------
// Kernel 0: split pw weights into fp16 hi/lo
// ---------------------------------------------------------------------------
__global__ void pw_split(const float* __restrict__ pw) {
    int i = blockIdx.x * 256 + threadIdx.x;   // 65536 elems
    float v = pw[i];
    __half h = __float2half_rn(v);
    g_pw_hi[i] = h;
    g_pw_lo[i] = __float2half_rn(v - __half2float(h));
}

// ---------------------------------------------------------------------------
// Kernel 1: global average pool
// ---------------------------------------------------------------------------
__global__ void pool_kernel(const float* __restrict__ x) {
    int bc = blockIdx.x;
    const float4* xp = (const float4*)(x + (size_t)bc * 4096);
    float s = 0.f;
    #pragma unroll 4
    for (int i = threadIdx.x; i < 1024; i += 256) {
        float4 v = xp[i];
        s += (v.x + v.y) + (v.z + v.w);
    }
    __shared__ float red[256];
    red[threadIdx.x] = s;
    __syncthreads();
    for (int off = 128; off > 0; off >>= 1) {
        if (threadIdx.x < off) red[threadIdx.x] += red[threadIdx.x + off];
        __syncthreads();
    }
    if (threadIdx.x == 0) g_pooled[bc] = red[0] * (1.f / 4096.f);
}

// ---------------------------------------------------------------------------
// Kernel 2: h = gelu(pooled @ w1^T + b1)
// ---------------------------------------------------------------------------
__global__ void mlp1_kernel(const float* __restrict__ w1, const float* __restrict__ b1) {
    int b = blockIdx.x;
    int j = threadIdx.x;   // 0..63
    __shared__ float p[256];
    for (int i = threadIdx.x; i < 256; i += 64) p[i] = g_pooled[b * 256 + i];
    __syncthreads();
    float s = b1[j];
    const float* wr = w1 + (size_t)j * 256;
    #pragma unroll 8
    for (int c = 0; c < 256; c++) s += p[c] * wr[c];
    g_h[b * 64 + j] = 0.5f * s * (1.0f + erff(s * 0.70710678118654752f));
}

// ---------------------------------------------------------------------------
// Kernel 3: fused[b,wi] = dw[wi] + b2[wi] + sum_j h[b,j]*w2[wi,j]
// ---------------------------------------------------------------------------
__global__ void __launch_bounds__(256) fuse_kernel(const float* __restrict__ dw,
                                                   const float* __restrict__ w2,
                                                   const float* __restrict__ b2) {
    __shared__ float hs[16 * 64];
    __shared__ float w2s[128 * 68];
    int tid = threadIdx.x;
    int wi0 = blockIdx.x * 128;

    *(float4*)(hs + tid * 4) = *(const float4*)(g_h + tid * 4);
    #pragma unroll
    for (int i = 0; i < 8; i++) {
        int lin = tid + i * 256;
        int r = lin >> 4, j4 = lin & 15;
        float4 v = *(const float4*)(w2 + (size_t)(wi0 + r) * 64 + j4 * 4);
        *(float4*)(w2s + r * 68 + j4 * 4) = v;
    }
    __syncthreads();

    int wiL = tid & 127;
    int bg = (tid >> 7) * 8;
    int wi = wi0 + wiL;
    float base = dw[wi] + b2[wi];
    float acc[8];
    #pragma unroll
    for (int bb = 0; bb < 8; bb++) acc[bb] = base;

    const float* wr = w2s + wiL * 68;
    #pragma unroll
    for (int j4 = 0; j4 < 16; j4++) {
        float4 w = *(const float4*)(wr + j4 * 4);
        #pragma unroll
        for (int bb = 0; bb < 8; bb++) {
            float4 h = *(const float4*)(hs + (bg + bb) * 64 + j4 * 4);
            acc[bb] += w.x * h.x + w.y * h.y + w.z * h.z + w.w * h.w;
        }
    }
    #pragma unroll
    for (int bb = 0; bb < 8; bb++)
        g_fused[(size_t)(bg + bb) * 12544 + wi] = acc[bb];
}

// ---------------------------------------------------------------------------
// Kernel 4: per-sample depthwise 7x7 conv, pad=3.
// Thread = 2 cols x 2 rows; epilogue stores packed fp16 (half2 as uint32).
// ---------------------------------------------------------------------------
__global__ void __launch_bounds__(256, 2) dw_kernel(const float* __restrict__ x) {
    int bc = blockIdx.y;
    int rowBase = blockIdx.x * 16;
    const float* xp = x + (size_t)bc * 4096;

    __shared__ __align__(16) float s[22 * 70];
    __shared__ float wsh[49];

    if (threadIdx.x < 49) wsh[threadIdx.x] = g_fused[bc * 49 + threadIdx.x];

    for (int i = threadIdx.x; i < 22 * 70; i += 256) {
        int r = i / 70, cc = i - r * 70;
        int gr = rowBase + r - 3, gc = cc - 3;
        s[i] = (gr >= 0 && gr < 64 && gc >= 0 && gc < 64) ? xp[gr * 64 + gc] : 0.f;
    }
    __syncthreads();

    float w[49];
    #pragma unroll
    for (int q = 0; q < 49; q++) w[q] = wsh[q];
    #pragma unroll
    for (int q = 0; q < 49; q++) asm volatile("" : "+f"(w[q]));

    int c0  = (threadIdx.x & 31) * 2;   // output cols c0, c0+1
    int lr0 = (threadIdx.x >> 5) * 2;   // local output rows lr0, lr0+1

    float acc[2][2] = {{0.f, 0.f}, {0.f, 0.f}};
    #pragma unroll
    for (int r = 0; r < 8; r++) {
        float v[8];
        const float* row = s + (lr0 + r) * 70 + c0;
        #pragma unroll
        for (int q = 0; q < 4; q++) *(float2*)&v[q * 2] = *(const float2*)(row + q * 2);
        #pragma unroll
        for (int dy = 0; dy < 2; dy++) {
            int ky = r - dy;
            if (ky >= 0 && ky < 7) {
                #pragma unroll
                for (int kx = 0; kx < 7; kx++) {
                    float wv = w[ky * 7 + kx];
                    acc[dy][0] += v[kx] * wv;
                    acc[dy][1] += v[kx + 1] * wv;
                }
            }
        }
    }

    #pragma unroll
    for (int dy = 0; dy < 2; dy++) {
        int row = rowBase + lr0 + dy;
        uint32_t idx = (uint32_t)bc * 4096u + (uint32_t)row * 64u + (uint32_t)c0;
        __half2 hp;
        hp.x = __float2half_rn(acc[dy][0]);
        hp.y = __float2half_rn(acc[dy][1]);
        *(uint32_t*)&g_bh[idx] = *(uint32_t*)&hp;
    }
}

// ---------------------------------------------------------------------------
// Kernel 5: pointwise GEMM via mma.sync fp16 2-pass (A = hi+lo, B = fp16),
// 3-stage cp.async pipeline.
//   Stage (28672 B): A_hi[128x80B] @0, A_lo @10240, B[32x256B] @20480.
// ---------------------------------------------------------------------------
__global__ void __launch_bounds__(256) pw_gemm_mma(float* __restrict__ out) {
    extern __shared__ __align__(128) char sm[];
    const uint32_t smb = smem_u32(sm);
    const uint32_t STAGE = 28672;

    const int tid = threadIdx.x;
    const int wid = tid >> 5, lane = tid & 31;
    const int warp_m = wid & 1;
    const int warp_n = wid >> 1;
    const int n0 = blockIdx.x * 128;
    const int m0 = blockIdx.y * 128;
    const int b  = blockIdx.z;

    float acc[4][4][4];
    #pragma unroll
    for (int i = 0; i < 4; i++)
        #pragma unroll
        for (int j = 0; j < 4; j++)
            #pragma unroll
            for (int q = 0; q < 4; q++) acc[i][j][q] = 0.f;

    const int lm16 = lane & 15, lhi = lane >> 4;
    const uint32_t aRowOff = (uint32_t)(warp_m * 64 + lm16) * 80 + (uint32_t)lhi * 16;
    const int bN = warp_n * 32 + lhi * 8;

    float* ob = out + (size_t)b * 1048576;

    auto issue = [&](int kc, uint32_t sbase) {
        // A: 1024 x 16B (2 halves x 128 rows x 4 chunks)
        #pragma unroll
        for (int i = 0; i < 4; i++) {
            int lin = tid + i * 256;
            int half = lin >> 9;
            int c = lin & 511;
            int r = c >> 2, j = c & 3;
            const __half* src =
                (half ? g_pw_lo : g_pw_hi) + (size_t)(m0 + r) * 256 + kc * 32 + j * 8;
            cp16(sbase + half * 10240 + r * 80 + j * 16, src);
        }
        // B: 512 x 16B (32 k-rows x 16 chunks), swizzled dst
        #pragma unroll
        for (int i = 0; i < 2; i++) {
            int lin = tid + i * 256;
            int k = lin >> 4, j16 = lin & 15;
            const __half* src = g_bh + (size_t)b * 1048576
                + (size_t)(kc * 32 + k) * 4096 + n0 + j16 * 8;
            cp16(sbase + 20480 + (uint32_t)k * 256
                 + (uint32_t)((j16 ^ (k & 7)) * 16), src);
        }
        cp_commit();
    };

    // prologue: fill 2 of 3 stages
    issue(0, smb);
    issue(1, smb + STAGE);

    for (int kc = 0; kc < 8; kc++) {
        const uint32_t sbase = smb + (uint32_t)(kc % 3) * STAGE;
        if (kc == 7) cp_wait0(); else cp_wait1();
        __syncthreads();                       // stage kc ready; compute(kc-1) done
        if (kc < 6) issue(kc + 2, smb + (uint32_t)((kc + 2) % 3) * STAGE);

        const uint32_t aHi = sbase, aLo = sbase + 10240;
        const uint32_t bB  = sbase + 20480;
        #pragma unroll
        for (int ks = 0; ks < 2; ks++) {
            uint32_t bf[2][4];
            #pragma unroll
            for (int p = 0; p < 2; p++) {
                int k = ks * 16 + lm16;
                int n = bN + p * 16;
                uint32_t off = (uint32_t)k * 256
                             + (uint32_t)(((n >> 3) ^ (k & 7)) * 16);
                ldsm_x4_t(bf[p], bB + off);
            }
            #pragma unroll
            for (int pass = 0; pass < 2; pass++) {
                const uint32_t aBase = pass ? aLo : aHi;
                uint32_t af[4][4];
                #pragma unroll
                for (int mi = 0; mi < 4; mi++)
                    ldsm_x4(af[mi], aBase + aRowOff + (uint32_t)mi * (16 * 80)
                                   + (uint32_t)ks * 32);
                #pragma unroll
                for (int mi = 0; mi < 4; mi++) {
                    #pragma unroll
                    for (int p = 0; p < 2; p++) {
                        mma_f16(acc[mi][2 * p],     af[mi], &bf[p][0]);
                        mma_f16(acc[mi][2 * p + 1], af[mi], &bf[p][2]);
                    }
                }
            }
        }
    }

    // epilogue
    const int rowBase = m0 + warp_m * 64 + (lane >> 2);
    const int colBase = n0 + warp_n * 32 + (lane & 3) * 2;
    #pragma unroll
    for (int mi = 0; mi < 4; mi++) {
        #pragma unroll
        for (int ni = 0; ni < 4; ni++) {
            int r = rowBase + mi * 16;
            int c = colBase + ni * 8;
            *(float2*)&ob[(size_t)r * 4096 + c] =
                make_float2(acc[mi][ni][0], acc[mi][ni][1]);
            *(float2*)&ob[(size_t)(r + 8) * 4096 + c] =
                make_float2(acc[mi][ni][2], acc[mi][ni][3]);
        }
    }
}

// ---------------------------------------------------------------------------
// launch
// ---------------------------------------------------------------------------
extern "C" void kernel_launch(void* const* d_in, const int* in_sizes, int n_in,
                              void* d_out, int out_size) {
    const float* x   = (const float*)d_in[0];  // [16,256,64,64]
    const float* dw  = (const float*)d_in[1];  // [256,1,7,7]
    const float* pwm = (const float*)d_in[2];  // [256,256]
    const float* w1  = (const float*)d_in[3];  // [64,256]
    const float* b1  = (const float*)d_in[4];  // [64]
    const float* w2  = (const float*)d_in[5];  // [12544,64]
    const float* b2  = (const float*)d_in[6];  // [12544]
    float* out = (float*)d_out;                // [16,256,64,64] fp32

    cudaFuncSetAttribute(pw_gemm_mma, cudaFuncAttributeMaxDynamicSharedMemorySize, 86016);

    pw_split<<<256, 256>>>(pwm);
    pool_kernel<<<4096, 256>>>(x);
    mlp1_kernel<<<16, 64>>>(w1, b1);
    fuse_kernel<<<98, 256>>>(dw, w2, b2);
    dw_kernel<<<dim3(4, 4096), 256>>>(x);
    pw_gemm_mma<<<dim3(32, 2, 16), 256, 86016>>>(out);
}

// round 9
// speedup vs baseline: 2.3026x; 1.1680x over previous
#include <cuda_runtime.h>
#include <cuda_fp16.h>
#include <math.h>
#include <stdint.h>

#define DINLINE __device__ __forceinline__

// Problem constants: B=16, C=256, H=W=64, K=7, C/4=64, C*K*K=12544

// ---- scratch (static device allocations: allowed) ----
__device__ __align__(128) float g_pooled[16 * 256];            // [B, C]
__device__ __align__(128) float g_h[16 * 64];                  // [B, C/4]
__device__ __align__(128) float g_fused[16 * 256 * 49];        // [B, C, 49]
__device__ __align__(128) __half g_bh[16u*256u*64u*64u];       // dw out, fp16 (32 MB)
__device__ __align__(128) __half g_pwh[256 * 256];             // fp16 pw weights

// ===========================================================================
// sm_80-era PTX helpers (legal on plain sm_100 target)
// ===========================================================================
DINLINE uint32_t smem_u32(const void* p) {
    uint32_t a;
    asm("{ .reg .u64 t; cvta.to.shared.u64 t, %1; cvt.u32.u64 %0, t; }" : "=r"(a) : "l"(p));
    return a;
}
DINLINE void ldsm_x4(uint32_t* r, uint32_t addr) {
    asm volatile("ldmatrix.sync.aligned.m8n8.x4.shared.b16 {%0,%1,%2,%3}, [%4];"
                 : "=r"(r[0]), "=r"(r[1]), "=r"(r[2]), "=r"(r[3]) : "r"(addr));
}
DINLINE void ldsm_x4_t(uint32_t* r, uint32_t addr) {
    asm volatile("ldmatrix.sync.aligned.m8n8.x4.trans.shared.b16 {%0,%1,%2,%3}, [%4];"
                 : "=r"(r[0]), "=r"(r[1]), "=r"(r[2]), "=r"(r[3]) : "r"(addr));
}
DINLINE void mma_f16(float* d, const uint32_t* a, const uint32_t* b) {
    asm volatile(
        "mma.sync.aligned.m16n8k16.row.col.f32.f16.f16.f32 "
        "{%0,%1,%2,%3}, {%4,%5,%6,%7}, {%8,%9}, {%0,%1,%2,%3};"
        : "+f"(d[0]), "+f"(d[1]), "+f"(d[2]), "+f"(d[3])
        : "r"(a[0]), "r"(a[1]), "r"(a[2]), "r"(a[3]), "r"(b[0]), "r"(b[1]));
}
DINLINE void cp16(uint32_t dst, const void* src) {
    asm volatile("cp.async.cg.shared.global [%0], [%1], 16;"
                 :: "r"(dst), "l"(__cvta_generic_to_global(src)));
}
DINLINE void cp_commit() { asm volatile("cp.async.commit_group;" ::: "memory"); }
DINLINE void cp_wait0()  { asm volatile("cp.async.wait_group 0;" ::: "memory"); }
DINLINE void cp_wait1()  { asm volatile("cp.async.wait_group 1;" ::: "memory"); }

// ---------------------------------------------------------------------------
// Kernel 0: pw weights -> fp16
// ---------------------------------------------------------------------------
__global__ void pw_split(const float* __restrict__ pw) {
    int i = blockIdx.x * 256 + threadIdx.x;   // 65536 elems
    g_pwh[i] = __float2half_rn(pw[i]);
}

// ---------------------------------------------------------------------------
// Kernel 1: global average pool
// ---------------------------------------------------------------------------
__global__ void pool_kernel(const float* __restrict__ x) {
    int bc = blockIdx.x;
    const float4* xp = (const float4*)(x + (size_t)bc * 4096);
    float s = 0.f;
    #pragma unroll 4
    for (int i = threadIdx.x; i < 1024; i += 256) {
        float4 v = xp[i];
        s += (v.x + v.y) + (v.z + v.w);
    }
    __shared__ float red[256];
    red[threadIdx.x] = s;
    __syncthreads();
    for (int off = 128; off > 0; off >>= 1) {
        if (threadIdx.x < off) red[threadIdx.x] += red[threadIdx.x + off];
        __syncthreads();
    }
    if (threadIdx.x == 0) g_pooled[bc] = red[0] * (1.f / 4096.f);
}

// ---------------------------------------------------------------------------
// Kernel 2: h = gelu(pooled @ w1^T + b1)
// ---------------------------------------------------------------------------
__global__ void mlp1_kernel(const float* __restrict__ w1, const float* __restrict__ b1) {
    int b = blockIdx.x;
    int j = threadIdx.x;   // 0..63
    __shared__ float p[256];
    for (int i = threadIdx.x; i < 256; i += 64) p[i] = g_pooled[b * 256 + i];
    __syncthreads();
    float s = b1[j];
    const float* wr = w1 + (size_t)j * 256;
    #pragma unroll 8
    for (int c = 0; c < 256; c++) s += p[c] * wr[c];
    g_h[b * 64 + j] = 0.5f * s * (1.0f + erff(s * 0.70710678118654752f));
}

// ---------------------------------------------------------------------------
// Kernel 3: fused[b,wi] = dw[wi] + b2[wi] + sum_j h[b,j]*w2[wi,j]
// ---------------------------------------------------------------------------
__global__ void __launch_bounds__(256) fuse_kernel(const float* __restrict__ dw,
                                                   const float* __restrict__ w2,
                                                   const float* __restrict__ b2) {
    __shared__ float hs[16 * 64];
    __shared__ float w2s[128 * 68];
    int tid = threadIdx.x;
    int wi0 = blockIdx.x * 128;

    *(float4*)(hs + tid * 4) = *(const float4*)(g_h + tid * 4);
    #pragma unroll
    for (int i = 0; i < 8; i++) {
        int lin = tid + i * 256;
        int r = lin >> 4, j4 = lin & 15;
        float4 v = *(const float4*)(w2 + (size_t)(wi0 + r) * 64 + j4 * 4);
        *(float4*)(w2s + r * 68 + j4 * 4) = v;
    }
    __syncthreads();

    int wiL = tid & 127;
    int bg = (tid >> 7) * 8;
    int wi = wi0 + wiL;
    float base = dw[wi] + b2[wi];
    float acc[8];
    #pragma unroll
    for (int bb = 0; bb < 8; bb++) acc[bb] = base;

    const float* wr = w2s + wiL * 68;
    #pragma unroll
    for (int j4 = 0; j4 < 16; j4++) {
        float4 w = *(const float4*)(wr + j4 * 4);
        #pragma unroll
        for (int bb = 0; bb < 8; bb++) {
            float4 h = *(const float4*)(hs + (bg + bb) * 64 + j4 * 4);
            acc[bb] += w.x * h.x + w.y * h.y + w.z * h.z + w.w * h.w;
        }
    }
    #pragma unroll
    for (int bb = 0; bb < 8; bb++)
        g_fused[(size_t)(bg + bb) * 12544 + wi] = acc[bb];
}

// ---------------------------------------------------------------------------
// Kernel 4: per-sample depthwise 7x7 conv, pad=3.
// Thread = 2 cols x 2 rows; epilogue stores packed fp16 (half2 as uint32).
// ---------------------------------------------------------------------------
__global__ void __launch_bounds__(256, 2) dw_kernel(const float* __restrict__ x) {
    int bc = blockIdx.y;
    int rowBase = blockIdx.x * 16;
    const float* xp = x + (size_t)bc * 4096;

    __shared__ __align__(16) float s[22 * 70];
    __shared__ float wsh[49];

    if (threadIdx.x < 49) wsh[threadIdx.x] = g_fused[bc * 49 + threadIdx.x];

    for (int i = threadIdx.x; i < 22 * 70; i += 256) {
        int r = i / 70, cc = i - r * 70;
        int gr = rowBase + r - 3, gc = cc - 3;
        s[i] = (gr >= 0 && gr < 64 && gc >= 0 && gc < 64) ? xp[gr * 64 + gc] : 0.f;
    }
    __syncthreads();

    float w[49];
    #pragma unroll
    for (int q = 0; q < 49; q++) w[q] = wsh[q];
    #pragma unroll
    for (int q = 0; q < 49; q++) asm volatile("" : "+f"(w[q]));

    int c0  = (threadIdx.x & 31) * 2;   // output cols c0, c0+1
    int lr0 = (threadIdx.x >> 5) * 2;   // local output rows lr0, lr0+1

    float acc[2][2] = {{0.f, 0.f}, {0.f, 0.f}};
    #pragma unroll
    for (int r = 0; r < 8; r++) {
        float v[8];
        const float* row = s + (lr0 + r) * 70 + c0;
        #pragma unroll
        for (int q = 0; q < 4; q++) *(float2*)&v[q * 2] = *(const float2*)(row + q * 2);
        #pragma unroll
        for (int dy = 0; dy < 2; dy++) {
            int ky = r - dy;
            if (ky >= 0 && ky < 7) {
                #pragma unroll
                for (int kx = 0; kx < 7; kx++) {
                    float wv = w[ky * 7 + kx];
                    acc[dy][0] += v[kx] * wv;
                    acc[dy][1] += v[kx + 1] * wv;
                }
            }
        }
    }

    #pragma unroll
    for (int dy = 0; dy < 2; dy++) {
        int row = rowBase + lr0 + dy;
        uint32_t idx = (uint32_t)bc * 4096u + (uint32_t)row * 64u + (uint32_t)c0;
        __half2 hp;
        hp.x = __float2half_rn(acc[dy][0]);
        hp.y = __float2half_rn(acc[dy][1]);
        *(uint32_t*)&g_bh[idx] = *(uint32_t*)&hp;
    }
}

// ---------------------------------------------------------------------------
// Kernel 5: pointwise GEMM via mma.sync fp16 single pass, 3-stage cp.async.
//   Stage (18432 B): A[128x80B] @0, B[32x256B] @10240.
// ---------------------------------------------------------------------------
__global__ void __launch_bounds__(256) pw_gemm_mma(float* __restrict__ out) {
    extern __shared__ __align__(128) char sm[];
    const uint32_t smb = smem_u32(sm);
    const uint32_t STAGE = 18432;

    const int tid = threadIdx.x;
    const int wid = tid >> 5, lane = tid & 31;
    const int warp_m = wid & 1;
    const int warp_n = wid >> 1;
    const int n0 = blockIdx.x * 128;
    const int m0 = blockIdx.y * 128;
    const int b  = blockIdx.z;

    float acc[4][4][4];
    #pragma unroll
    for (int i = 0; i < 4; i++)
        #pragma unroll
        for (int j = 0; j < 4; j++)
            #pragma unroll
            for (int q = 0; q < 4; q++) acc[i][j][q] = 0.f;

    const int lm16 = lane & 15, lhi = lane >> 4;
    const uint32_t aRowOff = (uint32_t)(warp_m * 64 + lm16) * 80 + (uint32_t)lhi * 16;
    const int bN = warp_n * 32 + lhi * 8;

    float* ob = out + (size_t)b * 1048576;

    auto issue = [&](int kc, uint32_t sbase) {
        // A: 512 x 16B (128 rows x 4 chunks)
        #pragma unroll
        for (int i = 0; i < 2; i++) {
            int lin = tid + i * 256;
            int r = lin >> 2, j = lin & 3;
            const __half* src = g_pwh + (size_t)(m0 + r) * 256 + kc * 32 + j * 8;
            cp16(sbase + r * 80 + j * 16, src);
        }
        // B: 512 x 16B (32 k-rows x 16 chunks), swizzled dst
        #pragma unroll
        for (int i = 0; i < 2; i++) {
            int lin = tid + i * 256;
            int k = lin >> 4, j16 = lin & 15;
            const __half* src = g_bh + (size_t)b * 1048576
                + (size_t)(kc * 32 + k) * 4096 + n0 + j16 * 8;
            cp16(sbase + 10240 + (uint32_t)k * 256
                 + (uint32_t)((j16 ^ (k & 7)) * 16), src);
        }
        cp_commit();
    };

    // prologue: fill 2 of 3 stages
    issue(0, smb);
    issue(1, smb + STAGE);

    for (int kc = 0; kc < 8; kc++) {
        const uint32_t sbase = smb + (uint32_t)(kc % 3) * STAGE;
        if (kc == 7) cp_wait0(); else cp_wait1();
        __syncthreads();                       // stage kc ready; compute(kc-1) done
        if (kc < 6) issue(kc + 2, smb + (uint32_t)((kc + 2) % 3) * STAGE);

        const uint32_t aB = sbase, bB = sbase + 10240;
        #pragma unroll
        for (int ks = 0; ks < 2; ks++) {
            uint32_t bf[2][4];
            #pragma unroll
            for (int p = 0; p < 2; p++) {
                int k = ks * 16 + lm16;
                int n = bN + p * 16;
                uint32_t off = (uint32_t)k * 256
                             + (uint32_t)(((n >> 3) ^ (k & 7)) * 16);
                ldsm_x4_t(bf[p], bB + off);
            }
            uint32_t af[4][4];
            #pragma unroll
            for (int mi = 0; mi < 4; mi++)
                ldsm_x4(af[mi], aB + aRowOff + (uint32_t)mi * (16 * 80)
                               + (uint32_t)ks * 32);
            #pragma unroll
            for (int mi = 0; mi < 4; mi++) {
                #pragma unroll
                for (int p = 0; p < 2; p++) {
                    mma_f16(acc[mi][2 * p],     af[mi], &bf[p][0]);
                    mma_f16(acc[mi][2 * p + 1], af[mi], &bf[p][2]);
                }
            }
        }
    }

    // epilogue
    const int rowBase = m0 + warp_m * 64 + (lane >> 2);
    const int colBase = n0 + warp_n * 32 + (lane & 3) * 2;
    #pragma unroll
    for (int mi = 0; mi < 4; mi++) {
        #pragma unroll
        for (int ni = 0; ni < 4; ni++) {
            int r = rowBase + mi * 16;
            int c = colBase + ni * 8;
            *(float2*)&ob[(size_t)r * 4096 + c] =
                make_float2(acc[mi][ni][0], acc[mi][ni][1]);
            *(float2*)&ob[(size_t)(r + 8) * 4096 + c] =
                make_float2(acc[mi][ni][2], acc[mi][ni][3]);
        }
    }
}

// ---------------------------------------------------------------------------
// launch
// ---------------------------------------------------------------------------
extern "C" void kernel_launch(void* const* d_in, const int* in_sizes, int n_in,
                              void* d_out, int out_size) {
    const float* x   = (const float*)d_in[0];  // [16,256,64,64]
    const float* dw  = (const float*)d_in[1];  // [256,1,7,7]
    const float* pwm = (const float*)d_in[2];  // [256,256]
    const float* w1  = (const float*)d_in[3];  // [64,256]
    const float* b1  = (const float*)d_in[4];  // [64]
    const float* w2  = (const float*)d_in[5];  // [12544,64]
    const float* b2  = (const float*)d_in[6];  // [12544]
    float* out = (float*)d_out;                // [16,256,64,64] fp32

    cudaFuncSetAttribute(pw_gemm_mma, cudaFuncAttributeMaxDynamicSharedMemorySize, 55296);

    pw_split<<<256, 256>>>(pwm);
    pool_kernel<<<4096, 256>>>(x);
    mlp1_kernel<<<16, 64>>>(w1, b1);
    fuse_kernel<<<98, 256>>>(dw, w2, b2);
    dw_kernel<<<dim3(4, 4096), 256>>>(x);
    pw_gemm_mma<<<dim3(32, 2, 16), 256, 55296>>>(out);
}